// round 1
// baseline (speedup 1.0000x reference)
#include <cuda_runtime.h>
#include <math.h>

#define TWO_PI_F  6.28318530717958647692f
#define TWO_PI2_F 19.739208802178716f   /* 2*pi^2 */

#define NMAX 8192
#define PMAX 64
#define KPAD 520
#define CH 16
#define NCHUNK_MAX 32

// ---------- device scratch (no allocations allowed) ----------
__device__ float g_A[PMAX * NMAX];   // sf * <x_n, xi_p>, layout [p][n]
__device__ float g_B[PMAX * NMAX];   // sf * <y_m, xi_p>, layout [p][m]
__device__ float g_C[PMAX * KPAD];   // Re yhat[p][k]  (later *kft2)
__device__ float g_S[PMAX * KPAD];   // Im yhat[p][k]  (later *kft2)
__device__ float g_kft2[KPAD];       // 2*kft(h)/P, thresholded
__device__ unsigned int g_norm2max_bits;
__device__ int g_hmax;
__device__ float g_sf;

// ---------- init: zero accumulators + output, reset reductions ----------
__global__ void init_kernel(float* __restrict__ out, int M) {
    int i = blockIdx.x * blockDim.x + threadIdx.x;
    int stride = gridDim.x * blockDim.x;
    for (int j = i; j < PMAX * KPAD; j += stride) { g_C[j] = 0.f; g_S[j] = 0.f; }
    for (int j = i; j < M; j += stride) out[j] = 0.f;
    for (int j = i; j < KPAD; j += stride) g_kft2[j] = 0.f;
    if (i == 0) { g_norm2max_bits = 0u; g_hmax = 0; }
}

// ---------- max row norm over x and y ----------
__global__ void norm_kernel(const float* __restrict__ x, const float* __restrict__ y,
                            int N, int M, int d) {
    int i = blockIdx.x * blockDim.x + threadIdx.x;
    float v = 0.f;
    int T = N + M;
    if (i < T) {
        const float* row = (i < N) ? (x + (size_t)i * d) : (y + (size_t)(i - N) * d);
        float s = 0.f;
        for (int j = 0; j < d; j += 4) {
            float4 q = *reinterpret_cast<const float4*>(row + j);
            s = fmaf(q.x, q.x, s); s = fmaf(q.y, q.y, s);
            s = fmaf(q.z, q.z, s); s = fmaf(q.w, q.w, s);
        }
        v = s;
    }
#pragma unroll
    for (int off = 16; off > 0; off >>= 1)
        v = fmaxf(v, __shfl_xor_sync(0xffffffffu, v, off));
    if ((threadIdx.x & 31) == 0 && v > 0.f)
        atomicMax(&g_norm2max_bits, __float_as_uint(v));  // positive floats: bit order == value order
}

// ---------- Fourier coefficients, cutoff detection ----------
__global__ void kft_kernel(const float* __restrict__ scale, int P, float dd) {
    __shared__ float sred[512];
    int tid = threadIdx.x;
    float nm = sqrtf(__uint_as_float(g_norm2max_bits));
    float sf = 0.3f / nm;
    float sr = scale[0] * sf;
    float s2 = sr * sr;
    int h = tid + 1;                 // h = 1..512, only 1..511 used
    float kft = 0.f;
    if (h <= 511) {
        float hp = (float)h;
        float logv = 0.5f * dd * logf(TWO_PI2_F * s2)
                   + (dd - 1.f) * logf(hp)
                   - TWO_PI2_F * s2 * hp * hp
                   - lgammaf(0.5f * dd);
        kft = expf(logv);
    }
    sred[tid] = kft;
    __syncthreads();
    for (int s = 256; s > 0; s >>= 1) {
        if (tid < s) sred[tid] = fmaxf(sred[tid], sred[tid + s]);
        __syncthreads();
    }
    float maxv = sred[0];
    float thr = maxv * 1e-10f;
    bool keep = (h <= 511) && (maxv > 0.f) && (kft > thr);
    if (h <= 511) g_kft2[h] = keep ? kft * (2.f / (float)P) : 0.f;  // folds pair-symmetry x2 and 1/P
    if (keep) atomicMax(&g_hmax, h);
    if (tid == 0) { g_sf = sf; g_kft2[0] = 0.f; }
}

// ---------- projections: dst[p][n] = sf * <pts_n, xi_p> ----------
__global__ void proj_kernel(const float* __restrict__ pts, const float* __restrict__ xis,
                            int npts, int d, int which) {
    int p = blockIdx.y;
    int n = blockIdx.x * blockDim.x + threadIdx.x;
    if (n >= npts) return;
    const float4* row = reinterpret_cast<const float4*>(pts + (size_t)n * d);
    const float4* xi  = reinterpret_cast<const float4*>(xis + (size_t)p * d);
    float s = 0.f;
    int q = d >> 2;
    for (int j = 0; j < q; j++) {
        float4 a = row[j];
        float4 b = __ldg(xi + j);
        s = fmaf(a.x, b.x, s); s = fmaf(a.y, b.y, s);
        s = fmaf(a.z, b.z, s); s = fmaf(a.w, b.w, s);
    }
    float* dst = which ? g_B : g_A;
    dst[(size_t)p * npts + n] = s * g_sf;
}

// ---------- adjoint NDFT: yhat[p][k] = sum_n w_n e^{i 2pi k a_{p,n}}, k=1..hmax ----------
// block = (slice p, k-chunk of CH); recurrence over k, 2-way unroll over n for ILP.
__global__ void __launch_bounds__(256) adjoint_kernel(const float* __restrict__ w, int N) {
    int p = blockIdx.x;
    int chunk = blockIdx.y;
    int hmax = g_hmax;
    int nchunk = (hmax + CH - 1) / CH;
    if (chunk >= nchunk) return;
    int k0 = 1 + chunk * CH;
    float fk0 = (float)k0;
    const float* arow = g_A + (size_t)p * N;
    float Cacc[CH], Sacc[CH];
#pragma unroll
    for (int j = 0; j < CH; j++) { Cacc[j] = 0.f; Sacc[j] = 0.f; }
    int tid = threadIdx.x;
    for (int n0 = tid; n0 < N; n0 += 512) {
        int n1 = n0 + 256;
        float a0 = arow[n0];
        float w0 = w[n0];
        float a1 = (n1 < N) ? arow[n1] : 0.f;
        float w1 = (n1 < N) ? w[n1]   : 0.f;
        float u0s, u0c, u1s, u1c;
        __sincosf(TWO_PI_F * a0, &u0s, &u0c);       // |2pi a| <= ~1.9: accurate
        __sincosf(TWO_PI_F * a1, &u1s, &u1c);
        // anchor z = e^{i 2pi k0 a} via exact-ish frac(k0*a)
        float t0 = fk0 * a0;
        float e0 = fmaf(fk0, a0, -t0);
        float f0 = (t0 - rintf(t0)) + e0;
        float t1 = fk0 * a1;
        float e1 = fmaf(fk0, a1, -t1);
        float f1 = (t1 - rintf(t1)) + e1;
        float z0s, z0c, z1s, z1c;
        __sincosf(TWO_PI_F * f0, &z0s, &z0c);       // |arg| <= pi
        __sincosf(TWO_PI_F * f1, &z1s, &z1c);
#pragma unroll
        for (int j = 0; j < CH; j++) {
            Cacc[j] = fmaf(w0, z0c, Cacc[j]);
            Sacc[j] = fmaf(w0, z0s, Sacc[j]);
            Cacc[j] = fmaf(w1, z1c, Cacc[j]);
            Sacc[j] = fmaf(w1, z1s, Sacc[j]);
            float nc0 = fmaf(z0c, u0c, -z0s * u0s);
            float ns0 = fmaf(z0c, u0s,  z0s * u0c);
            z0c = nc0; z0s = ns0;
            float nc1 = fmaf(z1c, u1c, -z1s * u1s);
            float ns1 = fmaf(z1c, u1s,  z1s * u1c);
            z1c = nc1; z1s = ns1;
        }
    }
    // warp butterfly reduction, then 1 atomic per (k, component) per warp
#pragma unroll
    for (int j = 0; j < CH; j++) {
#pragma unroll
        for (int off = 16; off > 0; off >>= 1) {
            Cacc[j] += __shfl_xor_sync(0xffffffffu, Cacc[j], off);
            Sacc[j] += __shfl_xor_sync(0xffffffffu, Sacc[j], off);
        }
    }
    if ((tid & 31) == 0) {
        float* Cg = g_C + (size_t)p * KPAD + k0;
        float* Sg = g_S + (size_t)p * KPAD + k0;
#pragma unroll
        for (int j = 0; j < CH; j++) {
            atomicAdd(Cg + j, Cacc[j]);
            atomicAdd(Sg + j, Sacc[j]);
        }
    }
}

// ---------- fold kft2 into C,S in place ----------
__global__ void scale_cs_kernel(int P) {
    int idx = blockIdx.x * blockDim.x + threadIdx.x;
    if (idx >= P * KPAD) return;
    int k = idx % KPAD;
    float f = g_kft2[k];
    g_C[idx] *= f;
    g_S[idx] *= f;
}

// ---------- forward: out[m] += sum_p sum_k CW cos(2pi k b) + SW sin(2pi k b) ----------
__global__ void __launch_bounds__(256) forward_kernel(float* __restrict__ out,
                                                      int M, int P, int PG) {
    int m = blockIdx.x * blockDim.x + threadIdx.x;
    if (m >= M) return;
    int p0 = blockIdx.y * PG;
    int p1 = p0 + PG; if (p1 > P) p1 = P;
    int hmax = g_hmax;
    int nchunk = (hmax + CH - 1) / CH;
    int KTOT = nchunk * CH;
    float acc0 = 0.f, acc1 = 0.f, acc2 = 0.f, acc3 = 0.f;
    int p = p0;
    for (; p + 1 < p1; p += 2) {   // 2 slices in flight for ILP
        float ba = g_B[(size_t)p * M + m];
        float bb = g_B[(size_t)(p + 1) * M + m];
        float uas, uac, ubs, ubc;
        __sincosf(TWO_PI_F * ba, &uas, &uac);
        __sincosf(TWO_PI_F * bb, &ubs, &ubc);
        float zac = uac, zas = uas, zbc = ubc, zbs = ubs;   // z at k=1
        const float* Ca = g_C + (size_t)p * KPAD;
        const float* Sa = g_S + (size_t)p * KPAD;
        const float* Cb = Ca + KPAD;
        const float* Sb = Sa + KPAD;
#pragma unroll 4
        for (int k = 1; k <= KTOT; k++) {
            acc0 = fmaf(__ldg(Ca + k), zac, acc0);
            acc1 = fmaf(__ldg(Sa + k), zas, acc1);
            acc2 = fmaf(__ldg(Cb + k), zbc, acc2);
            acc3 = fmaf(__ldg(Sb + k), zbs, acc3);
            float nac = fmaf(zac, uac, -zas * uas);
            float nas = fmaf(zac, uas,  zas * uac);
            zac = nac; zas = nas;
            float nbc = fmaf(zbc, ubc, -zbs * ubs);
            float nbs = fmaf(zbc, ubs,  zbs * ubc);
            zbc = nbc; zbs = nbs;
        }
    }
    if (p < p1) {  // odd tail slice
        float ba = g_B[(size_t)p * M + m];
        float uas, uac;
        __sincosf(TWO_PI_F * ba, &uas, &uac);
        float zac = uac, zas = uas;
        const float* Ca = g_C + (size_t)p * KPAD;
        const float* Sa = g_S + (size_t)p * KPAD;
#pragma unroll 4
        for (int k = 1; k <= KTOT; k++) {
            acc0 = fmaf(__ldg(Ca + k), zac, acc0);
            acc1 = fmaf(__ldg(Sa + k), zas, acc1);
            float nac = fmaf(zac, uac, -zas * uas);
            float nas = fmaf(zac, uas,  zas * uac);
            zac = nac; zas = nas;
        }
    }
    atomicAdd(out + m, (acc0 + acc1) + (acc2 + acc3));
}

extern "C" void kernel_launch(void* const* d_in, const int* in_sizes, int n_in,
                              void* d_out, int out_size) {
    const float* x     = (const float*)d_in[0];
    const float* y     = (const float*)d_in[1];
    const float* w     = (const float*)d_in[2];
    const float* scale = (const float*)d_in[3];
    const float* xis   = (const float*)d_in[4];
    float* out = (float*)d_out;

    int N = in_sizes[2];                 // x_weights length
    int d = in_sizes[0] / N;             // 64
    int M = out_size;                    // targets
    int P = in_sizes[4] / d;             // slices

    init_kernel<<<256, 256>>>(out, M);
    norm_kernel<<<(N + M + 255) / 256, 256>>>(x, y, N, M, d);
    kft_kernel<<<1, 512>>>(scale, P, (float)d);
    proj_kernel<<<dim3((N + 255) / 256, P), 256>>>(x, xis, N, d, 0);
    proj_kernel<<<dim3((M + 255) / 256, P), 256>>>(y, xis, M, d, 1);
    adjoint_kernel<<<dim3(P, NCHUNK_MAX), 256>>>(w, N);
    scale_cs_kernel<<<(P * KPAD + 255) / 256, 256>>>(P);
    int PG = 8;
    int ngroups = (P + PG - 1) / PG;
    forward_kernel<<<dim3((M + 255) / 256, ngroups), 256>>>(out, M, P, PG);
}

// round 2
// speedup vs baseline: 1.5245x; 1.5245x over previous
#include <cuda_runtime.h>
#include <math.h>

#define TWO_PI_F  6.28318530717958647692f
#define TWO_PI2_F 19.739208802178716f   /* 2*pi^2 */

#define NMAX 8192
#define PMAX 64
#define KPAD 520
#define CH 16
#define NCHUNK_MAX 32

// ---------- device scratch (no allocations allowed) ----------
__device__ float g_A[PMAX * NMAX];   // sf * <x_n, xi_p>, layout [p][n]
__device__ float g_B[PMAX * NMAX];   // sf * <y_m, xi_p>, layout [p][m]
__device__ float g_C[PMAX * KPAD];   // Re yhat[p][k]  (later *kft2)
__device__ float g_S[PMAX * KPAD];   // Im yhat[p][k]  (later *kft2)
__device__ float g_kft2[KPAD];       // 2*kft(h)/P, thresholded
__device__ unsigned int g_norm2max_bits;
__device__ int g_hmax;
__device__ float g_sf;

// ---------- init: zero accumulators + output, reset reductions ----------
__global__ void init_kernel(float* __restrict__ out, int M) {
    int i = blockIdx.x * blockDim.x + threadIdx.x;
    int stride = gridDim.x * blockDim.x;
    for (int j = i; j < PMAX * KPAD; j += stride) { g_C[j] = 0.f; g_S[j] = 0.f; }
    for (int j = i; j < M; j += stride) out[j] = 0.f;
    for (int j = i; j < KPAD; j += stride) g_kft2[j] = 0.f;
    if (i == 0) { g_norm2max_bits = 0u; g_hmax = 0; }
}

// ---------- max row norm over x and y ----------
__global__ void norm_kernel(const float* __restrict__ x, const float* __restrict__ y,
                            int N, int M, int d) {
    int i = blockIdx.x * blockDim.x + threadIdx.x;
    float v = 0.f;
    int T = N + M;
    if (i < T) {
        const float* row = (i < N) ? (x + (size_t)i * d) : (y + (size_t)(i - N) * d);
        float s = 0.f;
        for (int j = 0; j < d; j += 4) {
            float4 q = *reinterpret_cast<const float4*>(row + j);
            s = fmaf(q.x, q.x, s); s = fmaf(q.y, q.y, s);
            s = fmaf(q.z, q.z, s); s = fmaf(q.w, q.w, s);
        }
        v = s;
    }
#pragma unroll
    for (int off = 16; off > 0; off >>= 1)
        v = fmaxf(v, __shfl_xor_sync(0xffffffffu, v, off));
    if ((threadIdx.x & 31) == 0 && v > 0.f)
        atomicMax(&g_norm2max_bits, __float_as_uint(v));  // positive floats: bit order == value order
}

// ---------- Fourier coefficients, cutoff detection ----------
__global__ void kft_kernel(const float* __restrict__ scale, int P, float dd) {
    __shared__ float sred[512];
    int tid = threadIdx.x;
    float nm = sqrtf(__uint_as_float(g_norm2max_bits));
    float sf = 0.3f / nm;
    float sr = scale[0] * sf;
    float s2 = sr * sr;
    int h = tid + 1;                 // h = 1..512, only 1..511 used
    float kft = 0.f;
    if (h <= 511) {
        float hp = (float)h;
        float logv = 0.5f * dd * logf(TWO_PI2_F * s2)
                   + (dd - 1.f) * logf(hp)
                   - TWO_PI2_F * s2 * hp * hp
                   - lgammaf(0.5f * dd);
        kft = expf(logv);
    }
    sred[tid] = kft;
    __syncthreads();
    for (int s = 256; s > 0; s >>= 1) {
        if (tid < s) sred[tid] = fmaxf(sred[tid], sred[tid + s]);
        __syncthreads();
    }
    float maxv = sred[0];
    float thr = maxv * 1e-10f;
    bool keep = (h <= 511) && (maxv > 0.f) && (kft > thr);
    if (h <= 511) g_kft2[h] = keep ? kft * (2.f / (float)P) : 0.f;  // folds pair-symmetry x2 and 1/P
    if (keep) atomicMax(&g_hmax, h);
    if (tid == 0) { g_sf = sf; g_kft2[0] = 0.f; }
}

// ---------- projections v2: register-blocked mini-GEMM ----------
// Block: 256 threads, each thread owns one point row, accumulates ALL P=64
// projections in registers. xi staged once in smem; xi reads are warp-uniform
// LDS.128 broadcasts. Row read exactly once (16x LDG.128). Output coalesced.
__global__ void __launch_bounds__(256) proj2_kernel(const float* __restrict__ pts,
                                                    const float* __restrict__ xis,
                                                    int npts, int which) {
    __shared__ float xi_s[PMAX * 64];   // 16 KB
    int tid = threadIdx.x;
    // cooperative coalesced load of xi (4096 floats = 1024 float4)
    {
        const float4* src = reinterpret_cast<const float4*>(xis);
        float4* dst4 = reinterpret_cast<float4*>(xi_s);
        for (int i = tid; i < PMAX * 16; i += 256) dst4[i] = src[i];
    }
    __syncthreads();

    int n = blockIdx.x * 256 + tid;
    bool active = (n < npts);
    const float4* row = reinterpret_cast<const float4*>(pts + (size_t)n * 64);

    float acc[PMAX];
#pragma unroll
    for (int p = 0; p < PMAX; p++) acc[p] = 0.f;

    for (int j4 = 0; j4 < 16; j4++) {
        float4 rv = active ? row[j4] : make_float4(0.f, 0.f, 0.f, 0.f);
#pragma unroll
        for (int p = 0; p < PMAX; p++) {
            float4 xv = *reinterpret_cast<const float4*>(xi_s + p * 64 + j4 * 4);
            float s = acc[p];
            s = fmaf(rv.x, xv.x, s);
            s = fmaf(rv.y, xv.y, s);
            s = fmaf(rv.z, xv.z, s);
            s = fmaf(rv.w, xv.w, s);
            acc[p] = s;
        }
    }

    if (!active) return;
    float sf = g_sf;
    float* dst = which ? g_B : g_A;
#pragma unroll
    for (int p = 0; p < PMAX; p++)
        dst[(size_t)p * npts + n] = acc[p] * sf;   // coalesced per p
}

// ---------- adjoint NDFT: yhat[p][k] = sum_n w_n e^{i 2pi k a_{p,n}}, k=1..hmax ----------
// block = (slice p, k-chunk of CH); recurrence over k, 2-way unroll over n for ILP.
__global__ void __launch_bounds__(256) adjoint_kernel(const float* __restrict__ w, int N) {
    int p = blockIdx.x;
    int chunk = blockIdx.y;
    int hmax = g_hmax;
    int nchunk = (hmax + CH - 1) / CH;
    if (chunk >= nchunk) return;
    int k0 = 1 + chunk * CH;
    float fk0 = (float)k0;
    const float* arow = g_A + (size_t)p * N;
    float Cacc[CH], Sacc[CH];
#pragma unroll
    for (int j = 0; j < CH; j++) { Cacc[j] = 0.f; Sacc[j] = 0.f; }
    int tid = threadIdx.x;
    for (int n0 = tid; n0 < N; n0 += 512) {
        int n1 = n0 + 256;
        float a0 = arow[n0];
        float w0 = w[n0];
        float a1 = (n1 < N) ? arow[n1] : 0.f;
        float w1 = (n1 < N) ? w[n1]   : 0.f;
        float u0s, u0c, u1s, u1c;
        __sincosf(TWO_PI_F * a0, &u0s, &u0c);       // |2pi a| <= ~1.9: accurate
        __sincosf(TWO_PI_F * a1, &u1s, &u1c);
        // anchor z = e^{i 2pi k0 a} via exact-ish frac(k0*a)
        float t0 = fk0 * a0;
        float e0 = fmaf(fk0, a0, -t0);
        float f0 = (t0 - rintf(t0)) + e0;
        float t1 = fk0 * a1;
        float e1 = fmaf(fk0, a1, -t1);
        float f1 = (t1 - rintf(t1)) + e1;
        float z0s, z0c, z1s, z1c;
        __sincosf(TWO_PI_F * f0, &z0s, &z0c);       // |arg| <= pi
        __sincosf(TWO_PI_F * f1, &z1s, &z1c);
#pragma unroll
        for (int j = 0; j < CH; j++) {
            Cacc[j] = fmaf(w0, z0c, Cacc[j]);
            Sacc[j] = fmaf(w0, z0s, Sacc[j]);
            Cacc[j] = fmaf(w1, z1c, Cacc[j]);
            Sacc[j] = fmaf(w1, z1s, Sacc[j]);
            float nc0 = fmaf(z0c, u0c, -z0s * u0s);
            float ns0 = fmaf(z0c, u0s,  z0s * u0c);
            z0c = nc0; z0s = ns0;
            float nc1 = fmaf(z1c, u1c, -z1s * u1s);
            float ns1 = fmaf(z1c, u1s,  z1s * u1c);
            z1c = nc1; z1s = ns1;
        }
    }
    // warp butterfly reduction, then 1 atomic per (k, component) per warp
#pragma unroll
    for (int j = 0; j < CH; j++) {
#pragma unroll
        for (int off = 16; off > 0; off >>= 1) {
            Cacc[j] += __shfl_xor_sync(0xffffffffu, Cacc[j], off);
            Sacc[j] += __shfl_xor_sync(0xffffffffu, Sacc[j], off);
        }
    }
    if ((tid & 31) == 0) {
        float* Cg = g_C + (size_t)p * KPAD + k0;
        float* Sg = g_S + (size_t)p * KPAD + k0;
#pragma unroll
        for (int j = 0; j < CH; j++) {
            atomicAdd(Cg + j, Cacc[j]);
            atomicAdd(Sg + j, Sacc[j]);
        }
    }
}

// ---------- fold kft2 into C,S in place ----------
__global__ void scale_cs_kernel(int P) {
    int idx = blockIdx.x * blockDim.x + threadIdx.x;
    if (idx >= P * KPAD) return;
    int k = idx % KPAD;
    float f = g_kft2[k];
    g_C[idx] *= f;
    g_S[idx] *= f;
}

// ---------- forward: out[m] += sum_p sum_k CW cos(2pi k b) + SW sin(2pi k b) ----------
__global__ void __launch_bounds__(256) forward_kernel(float* __restrict__ out,
                                                      int M, int P, int PG) {
    int m = blockIdx.x * blockDim.x + threadIdx.x;
    if (m >= M) return;
    int p0 = blockIdx.y * PG;
    int p1 = p0 + PG; if (p1 > P) p1 = P;
    int hmax = g_hmax;
    int nchunk = (hmax + CH - 1) / CH;
    int KTOT = nchunk * CH;
    float acc0 = 0.f, acc1 = 0.f, acc2 = 0.f, acc3 = 0.f;
    int p = p0;
    for (; p + 1 < p1; p += 2) {   // 2 slices in flight for ILP
        float ba = g_B[(size_t)p * M + m];
        float bb = g_B[(size_t)(p + 1) * M + m];
        float uas, uac, ubs, ubc;
        __sincosf(TWO_PI_F * ba, &uas, &uac);
        __sincosf(TWO_PI_F * bb, &ubs, &ubc);
        float zac = uac, zas = uas, zbc = ubc, zbs = ubs;   // z at k=1
        const float* Ca = g_C + (size_t)p * KPAD;
        const float* Sa = g_S + (size_t)p * KPAD;
        const float* Cb = Ca + KPAD;
        const float* Sb = Sa + KPAD;
#pragma unroll 4
        for (int k = 1; k <= KTOT; k++) {
            acc0 = fmaf(__ldg(Ca + k), zac, acc0);
            acc1 = fmaf(__ldg(Sa + k), zas, acc1);
            acc2 = fmaf(__ldg(Cb + k), zbc, acc2);
            acc3 = fmaf(__ldg(Sb + k), zbs, acc3);
            float nac = fmaf(zac, uac, -zas * uas);
            float nas = fmaf(zac, uas,  zas * uac);
            zac = nac; zas = nas;
            float nbc = fmaf(zbc, ubc, -zbs * ubs);
            float nbs = fmaf(zbc, ubs,  zbs * ubc);
            zbc = nbc; zbs = nbs;
        }
    }
    if (p < p1) {  // odd tail slice
        float ba = g_B[(size_t)p * M + m];
        float uas, uac;
        __sincosf(TWO_PI_F * ba, &uas, &uac);
        float zac = uac, zas = uas;
        const float* Ca = g_C + (size_t)p * KPAD;
        const float* Sa = g_S + (size_t)p * KPAD;
#pragma unroll 4
        for (int k = 1; k <= KTOT; k++) {
            acc0 = fmaf(__ldg(Ca + k), zac, acc0);
            acc1 = fmaf(__ldg(Sa + k), zas, acc1);
            float nac = fmaf(zac, uac, -zas * uas);
            float nas = fmaf(zac, uas,  zas * uac);
            zac = nac; zas = nas;
        }
    }
    atomicAdd(out + m, (acc0 + acc1) + (acc2 + acc3));
}

extern "C" void kernel_launch(void* const* d_in, const int* in_sizes, int n_in,
                              void* d_out, int out_size) {
    const float* x     = (const float*)d_in[0];
    const float* y     = (const float*)d_in[1];
    const float* w     = (const float*)d_in[2];
    const float* scale = (const float*)d_in[3];
    const float* xis   = (const float*)d_in[4];
    float* out = (float*)d_out;

    int N = in_sizes[2];                 // x_weights length
    int d = in_sizes[0] / N;             // 64
    int M = out_size;                    // targets
    int P = in_sizes[4] / d;             // slices

    init_kernel<<<256, 256>>>(out, M);
    norm_kernel<<<(N + M + 255) / 256, 256>>>(x, y, N, M, d);
    kft_kernel<<<1, 512>>>(scale, P, (float)d);
    proj2_kernel<<<(N + 255) / 256, 256>>>(x, xis, N, 0);
    proj2_kernel<<<(M + 255) / 256, 256>>>(y, xis, M, 1);
    adjoint_kernel<<<dim3(P, NCHUNK_MAX), 256>>>(w, N);
    scale_cs_kernel<<<(P * KPAD + 255) / 256, 256>>>(P);
    int PG = 8;
    int ngroups = (P + PG - 1) / PG;
    forward_kernel<<<dim3((M + 255) / 256, ngroups), 256>>>(out, M, P, PG);
}

// round 3
// speedup vs baseline: 1.8471x; 1.2117x over previous
#include <cuda_runtime.h>
#include <math.h>

#define TWO_PI_F  6.28318530717958647692f
#define TWO_PI2_F 19.739208802178716f   /* 2*pi^2 */

#define NMAX 8192
#define PMAX 64
#define KPAD 520
#define CH 16
#define NCHUNK_MAX 32
#define PCH 16            /* slices per proj block */

typedef unsigned long long u64p;

// ---------- packed f32x2 helpers ----------
__device__ __forceinline__ u64p pk2(float lo, float hi) {
    u64p r; asm("mov.b64 %0, {%1, %2};" : "=l"(r) : "f"(lo), "f"(hi)); return r;
}
__device__ __forceinline__ void upk2(u64p v, float& lo, float& hi) {
    asm("mov.b64 {%0, %1}, %2;" : "=f"(lo), "=f"(hi) : "l"(v));
}
__device__ __forceinline__ u64p fma2(u64p a, u64p b, u64p c) {
    u64p d; asm("fma.rn.f32x2 %0, %1, %2, %3;" : "=l"(d) : "l"(a), "l"(b), "l"(c)); return d;
}

// ---------- device scratch (no allocations allowed) ----------
__device__ float g_A[PMAX * NMAX];    // sf * <x_n, xi_p>, layout [p][n]
__device__ float g_B[PMAX * NMAX];    // sf * <y_m, xi_p>, layout [p][m]
__device__ float g_C[PMAX * KPAD];    // Re yhat[p][k]
__device__ float g_S[PMAX * KPAD];    // Im yhat[p][k]
__device__ float2 g_CS[PMAX * KPAD];  // interleaved (C*kft2, S*kft2), slot j = k-1
__device__ float g_kft2[KPAD];        // 2*kft(h)/P, thresholded
__device__ unsigned int g_norm2max_bits;
__device__ int g_hmax;
__device__ float g_sf;

// ---------- init ----------
__global__ void init_kernel(float* __restrict__ out, int M) {
    int i = blockIdx.x * blockDim.x + threadIdx.x;
    int stride = gridDim.x * blockDim.x;
    for (int j = i; j < PMAX * KPAD; j += stride) { g_C[j] = 0.f; g_S[j] = 0.f; }
    for (int j = i; j < M; j += stride) out[j] = 0.f;
    for (int j = i; j < KPAD; j += stride) g_kft2[j] = 0.f;
    if (i == 0) { g_norm2max_bits = 0u; g_hmax = 0; }
}

// ---------- max row norm over x and y ----------
__global__ void norm_kernel(const float* __restrict__ x, const float* __restrict__ y,
                            int N, int M, int d) {
    int i = blockIdx.x * blockDim.x + threadIdx.x;
    float v = 0.f;
    int T = N + M;
    if (i < T) {
        const float* row = (i < N) ? (x + (size_t)i * d) : (y + (size_t)(i - N) * d);
        float s = 0.f;
        for (int j = 0; j < d; j += 4) {
            float4 q = *reinterpret_cast<const float4*>(row + j);
            s = fmaf(q.x, q.x, s); s = fmaf(q.y, q.y, s);
            s = fmaf(q.z, q.z, s); s = fmaf(q.w, q.w, s);
        }
        v = s;
    }
#pragma unroll
    for (int off = 16; off > 0; off >>= 1)
        v = fmaxf(v, __shfl_xor_sync(0xffffffffu, v, off));
    if ((threadIdx.x & 31) == 0 && v > 0.f)
        atomicMax(&g_norm2max_bits, __float_as_uint(v));
}

// ---------- Fourier coefficients, cutoff ----------
__global__ void kft_kernel(const float* __restrict__ scale, int P, float dd) {
    __shared__ float sred[512];
    int tid = threadIdx.x;
    float nm = sqrtf(__uint_as_float(g_norm2max_bits));
    float sf = 0.3f / nm;
    float sr = scale[0] * sf;
    float s2 = sr * sr;
    int h = tid + 1;
    float kft = 0.f;
    if (h <= 511) {
        float hp = (float)h;
        float logv = 0.5f * dd * logf(TWO_PI2_F * s2)
                   + (dd - 1.f) * logf(hp)
                   - TWO_PI2_F * s2 * hp * hp
                   - lgammaf(0.5f * dd);
        kft = expf(logv);
    }
    sred[tid] = kft;
    __syncthreads();
    for (int s = 256; s > 0; s >>= 1) {
        if (tid < s) sred[tid] = fmaxf(sred[tid], sred[tid + s]);
        __syncthreads();
    }
    float maxv = sred[0];
    float thr = maxv * 1e-10f;
    bool keep = (h <= 511) && (maxv > 0.f) && (kft > thr);
    if (h <= 511) g_kft2[h] = keep ? kft * (2.f / (float)P) : 0.f;
    if (keep) atomicMax(&g_hmax, h);
    if (tid == 0) { g_sf = sf; g_kft2[0] = 0.f; }
}

// ---------- projections v3: P-chunked, x+y fused, full-chip grid ----------
__global__ void __launch_bounds__(256) proj3_kernel(const float* __restrict__ xpts,
                                                    const float* __restrict__ ypts,
                                                    const float* __restrict__ xis,
                                                    int N, int M, int P) {
    __shared__ float xi_s[PCH * 64];   // 4 KB
    int tid = threadIdx.x;
    int which = blockIdx.z;
    const float* pts = which ? ypts : xpts;
    int npts = which ? M : N;
    int pbase = blockIdx.y * PCH;

    {   // cooperative load of 16 xi rows (256 float4)
        const float4* src = reinterpret_cast<const float4*>(xis + (size_t)pbase * 64);
        float4* dst4 = reinterpret_cast<float4*>(xi_s);
        if (tid < PCH * 16) dst4[tid] = src[tid];
    }
    __syncthreads();

    int n = blockIdx.x * 256 + tid;
    if (n >= npts) return;
    const float4* row = reinterpret_cast<const float4*>(pts + (size_t)n * 64);

    float acc[PCH];
#pragma unroll
    for (int p = 0; p < PCH; p++) acc[p] = 0.f;

#pragma unroll
    for (int j4 = 0; j4 < 16; j4++) {
        float4 rv = row[j4];
#pragma unroll
        for (int p = 0; p < PCH; p++) {
            float4 xv = *reinterpret_cast<const float4*>(xi_s + p * 64 + j4 * 4);
            float s = acc[p];
            s = fmaf(rv.x, xv.x, s);
            s = fmaf(rv.y, xv.y, s);
            s = fmaf(rv.z, xv.z, s);
            s = fmaf(rv.w, xv.w, s);
            acc[p] = s;
        }
    }

    float sf = g_sf;
    float* dst = which ? g_B : g_A;
#pragma unroll
    for (int p = 0; p < PCH; p++) {
        int pg = pbase + p;
        if (pg < P) dst[(size_t)pg * npts + n] = acc[p] * sf;
    }
}

// ---------- adjoint: packed Chebyshev 3-term, 2 fma2 per (n,k) per stream ----------
__global__ void __launch_bounds__(256) adjoint_kernel(const float* __restrict__ w, int N) {
    int p = blockIdx.x;
    int chunk = blockIdx.y;
    int hmax = g_hmax;
    int nchunk = (hmax + CH - 1) / CH;
    if (chunk >= nchunk) return;
    int k0 = 1 + chunk * CH;
    float fk0 = (float)k0;
    const float* arow = g_A + (size_t)p * N;

    u64p accv[CH];
#pragma unroll
    for (int j = 0; j < CH; j++) accv[j] = 0ull;

    int tid = threadIdx.x;
    for (int n0 = tid; n0 < N; n0 += 512) {
        int n1 = n0 + 256;
        bool has1 = (n1 < N);
        float a0 = arow[n0];
        float w0 = w[n0];
        float a1 = has1 ? arow[n1] : 0.f;
        float w1 = has1 ? w[n1]   : 0.f;

        // u = e^{i 2pi a}, t2 = 2 cos(2pi a)
        float u0s, u0c, u1s, u1c;
        __sincosf(TWO_PI_F * a0, &u0s, &u0c);
        __sincosf(TWO_PI_F * a1, &u1s, &u1c);
        // anchor z_{k0} via frac trick
        float t0 = fk0 * a0;
        float e0 = fmaf(fk0, a0, -t0);
        float f0 = (t0 - rintf(t0)) + e0;
        float t1 = fk0 * a1;
        float e1 = fmaf(fk0, a1, -t1);
        float f1 = (t1 - rintf(t1)) + e1;
        float z0s, z0c, z1s, z1c;
        __sincosf(TWO_PI_F * f0, &z0s, &z0c);
        __sincosf(TWO_PI_F * f1, &z1s, &z1c);
        // z_{k0-1} = z_{k0} * conj(u)
        float zm0c = fmaf(z0c, u0c,  z0s * u0s);
        float zm0s = fmaf(z0s, u0c, -z0c * u0s);
        float zm1c = fmaf(z1c, u1c,  z1s * u1s);
        float zm1s = fmaf(z1s, u1c, -z1c * u1s);

        // packed states: v_0 = z_{k0}, v_{-1} = -z_{k0-1} (sigma_{-1} = -1)
        u64p v0c_ = pk2(z0c, z0s);
        u64p v0p_ = pk2(-zm0c, -zm0s);
        u64p v1c_ = pk2(z1c, z1s);
        u64p v1p_ = pk2(-zm1c, -zm1s);
        u64p t2v0  = pk2( 2.f * u0c,  2.f * u0c);
        u64p nt2v0 = pk2(-2.f * u0c, -2.f * u0c);
        u64p t2v1  = pk2( 2.f * u1c,  2.f * u1c);
        u64p nt2v1 = pk2(-2.f * u1c, -2.f * u1c);
        u64p wv0  = pk2( w0,  w0);
        u64p nwv0 = pk2(-w0, -w0);
        u64p wv1  = pk2( w1,  w1);
        u64p nwv1 = pk2(-w1, -w1);

        // sigma_j pattern [+,+,-,-]; rotation: v_{j+1} = (+/-)t2 v_j + v_{j-1}, sign [+,-,+,-]
#pragma unroll
        for (int j = 0; j < CH; j++) {
            const bool accpos = ((j & 2) == 0);
            const bool rotpos = ((j & 1) == 0);
            accv[j] = fma2(accpos ? wv0 : nwv0, v0c_, accv[j]);
            accv[j] = fma2(accpos ? wv1 : nwv1, v1c_, accv[j]);
            u64p v0n = fma2(rotpos ? t2v0 : nt2v0, v0c_, v0p_);
            v0p_ = v0c_; v0c_ = v0n;
            u64p v1n = fma2(rotpos ? t2v1 : nt2v1, v1c_, v1p_);
            v1p_ = v1c_; v1c_ = v1n;
        }
    }

    // warp butterfly reduction on packed halves, then atomics
#pragma unroll
    for (int j = 0; j < CH; j++) {
        float c, s;
        upk2(accv[j], c, s);
#pragma unroll
        for (int off = 16; off > 0; off >>= 1) {
            c += __shfl_xor_sync(0xffffffffu, c, off);
            s += __shfl_xor_sync(0xffffffffu, s, off);
        }
        if ((tid & 31) == 0) {
            atomicAdd(g_C + (size_t)p * KPAD + k0 + j, c);
            atomicAdd(g_S + (size_t)p * KPAD + k0 + j, s);
        }
    }
}

// ---------- fold kft2 into interleaved g_CS, slot j holds k=j+1 ----------
__global__ void scale_cs_kernel(int P) {
    int idx = blockIdx.x * blockDim.x + threadIdx.x;
    if (idx >= P * KPAD) return;
    int p = idx / KPAD;
    int j = idx % KPAD;
    int k = j + 1;
    float f = (k < KPAD) ? g_kft2[k] : 0.f;
    float c = (k < KPAD) ? g_C[(size_t)p * KPAD + k] : 0.f;
    float s = (k < KPAD) ? g_S[(size_t)p * KPAD + k] : 0.f;
    g_CS[idx] = make_float2(c * f, s * f);
}

// ---------- forward: packed Clenshaw, 2 fma2 + 0.5 LDG.128 per (m,p,k) ----------
__global__ void __launch_bounds__(256) forward_kernel(float* __restrict__ out,
                                                      int M, int P, int PG) {
    int m = blockIdx.x * blockDim.x + threadIdx.x;
    if (m >= M) return;
    int p0 = blockIdx.y * PG;
    int p1 = p0 + PG; if (p1 > P) p1 = P;
    int hmax = g_hmax;
    int KE = ((hmax + CH - 1) / CH) * CH;   // even, multiple of 16
    const u64p negv = pk2(-1.f, -1.f);

    float total = 0.f;
    int p = p0;
    for (; p + 1 < p1; p += 2) {
        float ba = g_B[(size_t)p * M + m];
        float bb = g_B[(size_t)(p + 1) * M + m];
        float sa, ca, sb, cb;
        __sincosf(TWO_PI_F * ba, &sa, &ca);
        __sincosf(TWO_PI_F * bb, &sb, &cb);
        u64p t2a = pk2(2.f * ca, 2.f * ca);
        u64p t2b = pk2(2.f * cb, 2.f * cb);
        u64p a1 = 0ull, a2 = 0ull, b1 = 0ull, b2 = 0ull;
        const float4* CA = reinterpret_cast<const float4*>(g_CS + (size_t)p * KPAD);
        const float4* CB = reinterpret_cast<const float4*>(g_CS + (size_t)(p + 1) * KPAD);
        for (int j = KE - 2; j >= 0; j -= 2) {
            float4 fa = __ldg(CA + (j >> 1));   // (C_{j+1},S_{j+1},C_{j+2},S_{j+2})
            float4 fb = __ldg(CB + (j >> 1));
            // k = j+2
            u64p ta = fma2(t2a, a1, pk2(fa.z, fa.w));
            u64p na = fma2(negv, a2, ta);
            a2 = a1; a1 = na;
            u64p tb = fma2(t2b, b1, pk2(fb.z, fb.w));
            u64p nb = fma2(negv, b2, tb);
            b2 = b1; b1 = nb;
            // k = j+1
            ta = fma2(t2a, a1, pk2(fa.x, fa.y));
            na = fma2(negv, a2, ta);
            a2 = a1; a1 = na;
            tb = fma2(t2b, b1, pk2(fb.x, fb.y));
            nb = fma2(negv, b2, tb);
            b2 = b1; b1 = nb;
        }
        float a1l, a1h, a2l, a2h, b1l, b1h, b2l, b2h;
        upk2(a1, a1l, a1h); upk2(a2, a2l, a2h);
        upk2(b1, b1l, b1h); upk2(b2, b2l, b2h);
        total += fmaf(ca, a1l, fmaf(sa, a1h, -a2l));
        total += fmaf(cb, b1l, fmaf(sb, b1h, -b2l));
    }
    if (p < p1) {   // tail slice
        float ba = g_B[(size_t)p * M + m];
        float sa, ca;
        __sincosf(TWO_PI_F * ba, &sa, &ca);
        u64p t2a = pk2(2.f * ca, 2.f * ca);
        u64p a1 = 0ull, a2 = 0ull;
        const float4* CA = reinterpret_cast<const float4*>(g_CS + (size_t)p * KPAD);
        for (int j = KE - 2; j >= 0; j -= 2) {
            float4 fa = __ldg(CA + (j >> 1));
            u64p ta = fma2(t2a, a1, pk2(fa.z, fa.w));
            u64p na = fma2(negv, a2, ta);
            a2 = a1; a1 = na;
            ta = fma2(t2a, a1, pk2(fa.x, fa.y));
            na = fma2(negv, a2, ta);
            a2 = a1; a1 = na;
        }
        float a1l, a1h, a2l, a2h;
        upk2(a1, a1l, a1h); upk2(a2, a2l, a2h);
        total += fmaf(ca, a1l, fmaf(sa, a1h, -a2l));
    }
    atomicAdd(out + m, total);
}

extern "C" void kernel_launch(void* const* d_in, const int* in_sizes, int n_in,
                              void* d_out, int out_size) {
    const float* x     = (const float*)d_in[0];
    const float* y     = (const float*)d_in[1];
    const float* w     = (const float*)d_in[2];
    const float* scale = (const float*)d_in[3];
    const float* xis   = (const float*)d_in[4];
    float* out = (float*)d_out;

    int N = in_sizes[2];
    int d = in_sizes[0] / N;
    int M = out_size;
    int P = in_sizes[4] / d;

    init_kernel<<<256, 256>>>(out, M);
    norm_kernel<<<(N + M + 255) / 256, 256>>>(x, y, N, M, d);
    kft_kernel<<<1, 512>>>(scale, P, (float)d);
    int nmax = (N > M) ? N : M;
    dim3 pgrid((nmax + 255) / 256, (P + PCH - 1) / PCH, 2);
    proj3_kernel<<<pgrid, 256>>>(x, y, xis, N, M, P);
    adjoint_kernel<<<dim3(P, NCHUNK_MAX), 256>>>(w, N);
    scale_cs_kernel<<<(P * KPAD + 255) / 256, 256>>>(P);
    int PG = 8;
    int ngroups = (P + PG - 1) / PG;
    forward_kernel<<<dim3((M + 255) / 256, ngroups), 256>>>(out, M, P, PG);
}

// round 4
// speedup vs baseline: 2.0411x; 1.1050x over previous
#include <cuda_runtime.h>
#include <math.h>

#define TWO_PI_F  6.28318530717958647692f
#define TWO_PI2_F 19.739208802178716f   /* 2*pi^2 */

#define NMAX 8192
#define PMAX 64
#define KPAD 520
#define CH 40              /* k per adjoint chunk */
#define YCH 13             /* ceil(511/40) */
#define ZSPLIT 4           /* N-splits in adjoint */
#define PROJ_PTS 128

typedef unsigned long long u64p;

// ---------- packed f32x2 helpers ----------
__device__ __forceinline__ u64p pk2(float lo, float hi) {
    u64p r; asm("mov.b64 %0, {%1, %2};" : "=l"(r) : "f"(lo), "f"(hi)); return r;
}
__device__ __forceinline__ void upk2(u64p v, float& lo, float& hi) {
    asm("mov.b64 {%0, %1}, %2;" : "=f"(lo), "=f"(hi) : "l"(v));
}
__device__ __forceinline__ u64p fma2(u64p a, u64p b, u64p c) {
    u64p d; asm("fma.rn.f32x2 %0, %1, %2, %3;" : "=l"(d) : "l"(a), "l"(b), "l"(c)); return d;
}

// ---------- device scratch ----------
__device__ float  g_A[PMAX * NMAX];    // sf * <x_n, xi_p>, [p][n]
__device__ float  g_B[PMAX * NMAX];    // sf * <y_m, xi_p>, [p][m]
__device__ float2 g_CS[PMAX * KPAD];   // (C*kft2, S*kft2), slot j = k-1
__device__ float  g_kft2[KPAD];        // 2*kft(h)/P, thresholded
__device__ float  g_blockmax[256];
__device__ int    g_hmax;
__device__ int    g_kmin;
__device__ float  g_sf;

// ---------- norm + init fused ----------
__global__ void norm_init_kernel(const float* __restrict__ x, const float* __restrict__ y,
                                 float* __restrict__ out, int N, int M, int d) {
    __shared__ float wmax[8];
    int i = blockIdx.x * blockDim.x + threadIdx.x;
    int stride = gridDim.x * blockDim.x;
    // zero g_CS and out (unconditional stripes)
    float2 z2 = make_float2(0.f, 0.f);
    for (int j = i; j < PMAX * KPAD; j += stride) g_CS[j] = z2;
    for (int j = i; j < M; j += stride) out[j] = 0.f;
    // row norm^2
    float v = 0.f;
    int T = N + M;
    if (i < T) {
        const float* row = (i < N) ? (x + (size_t)i * d) : (y + (size_t)(i - N) * d);
        float s = 0.f;
        for (int j = 0; j < d; j += 4) {
            float4 q = *reinterpret_cast<const float4*>(row + j);
            s = fmaf(q.x, q.x, s); s = fmaf(q.y, q.y, s);
            s = fmaf(q.z, q.z, s); s = fmaf(q.w, q.w, s);
        }
        v = s;
    }
#pragma unroll
    for (int off = 16; off > 0; off >>= 1)
        v = fmaxf(v, __shfl_xor_sync(0xffffffffu, v, off));
    if ((threadIdx.x & 31) == 0) wmax[threadIdx.x >> 5] = v;
    __syncthreads();
    if (threadIdx.x == 0) {
        float m = wmax[0];
#pragma unroll
        for (int wq = 1; wq < 8; wq++) m = fmaxf(m, wmax[wq]);
        g_blockmax[blockIdx.x] = m;
    }
}

// ---------- Fourier coefficients, cutoff ----------
__global__ void kft_kernel(const float* __restrict__ scale, int P, float dd, int nb) {
    __shared__ float sred[512];
    int tid = threadIdx.x;
    if (tid == 0) { g_hmax = 0; g_kmin = 0x7fffffff; }
    // reduce block maxima
    float bm = (tid < nb) ? g_blockmax[tid] : 0.f;
    sred[tid] = bm;
    __syncthreads();
    for (int s = 256; s > 0; s >>= 1) {
        if (tid < s) sred[tid] = fmaxf(sred[tid], sred[tid + s]);
        __syncthreads();
    }
    float nm = sqrtf(sred[0]);
    float sf = 0.3f / nm;
    float sr = scale[0] * sf;
    float s2 = sr * sr;
    int h = tid + 1;
    float kft = 0.f;
    if (h <= 511) {
        float hp = (float)h;
        float logv = 0.5f * dd * logf(TWO_PI2_F * s2)
                   + (dd - 1.f) * logf(hp)
                   - TWO_PI2_F * s2 * hp * hp
                   - lgammaf(0.5f * dd);
        kft = expf(logv);
    }
    __syncthreads();
    sred[tid] = kft;
    __syncthreads();
    for (int s = 256; s > 0; s >>= 1) {
        if (tid < s) sred[tid] = fmaxf(sred[tid], sred[tid + s]);
        __syncthreads();
    }
    float maxv = sred[0];
    float thr = maxv * 1e-10f;
    bool keep = (h <= 511) && (maxv > 0.f) && (kft > thr);
    if (h <= 511) g_kft2[h] = keep ? kft * (2.f / (float)P) : 0.f;
    if (keep) { atomicMax(&g_hmax, h); atomicMin(&g_kmin, h); }
    if (tid == 0) { g_sf = sf; g_kft2[0] = 0.f; }
    if (tid < 8) g_kft2[512 + tid] = 0.f;
}

// ---------- proj4: smem-staged, full P in one pass, packed fma2 ----------
__global__ void __launch_bounds__(256) proj4_kernel(const float* __restrict__ xpts,
                                                    const float* __restrict__ ypts,
                                                    const float* __restrict__ xis,
                                                    int N, int M, int P) {
    __shared__ float xi_t[64 * 66];          // [dim][p], row stride 66
    __shared__ float pts_s[PROJ_PTS * 65];   // [r][dim], row stride 65
    int tid = threadIdx.x;
    int which = blockIdx.y;
    const float* pts = which ? ypts : xpts;
    int npts = which ? M : N;
    int base = blockIdx.x * PROJ_PTS;

    // stage xi transposed: xi_t[d][p]
    for (int idx = tid; idx < 64 * 64; idx += 256) {
        int p = idx >> 6, dc = idx & 63;
        xi_t[dc * 66 + p] = (p < P) ? xis[idx] : 0.f;
    }
    // stage point rows (coalesced), zero-fill OOB
    for (int idx = tid; idx < PROJ_PTS * 16; idx += 256) {
        int r = idx >> 4, j4 = idx & 15;
        int n = base + r;
        float4 v = make_float4(0.f, 0.f, 0.f, 0.f);
        if (n < npts) v = *reinterpret_cast<const float4*>(pts + (size_t)n * 64 + j4 * 4);
        float* dp = pts_s + r * 65 + j4 * 4;
        dp[0] = v.x; dp[1] = v.y; dp[2] = v.z; dp[3] = v.w;
    }
    __syncthreads();

    int slot = tid & 63;
    int g = tid >> 6;                 // 4 p-groups of 16 ps
    const float* r0 = pts_s + slot * 65;
    const float* r1 = pts_s + (slot + 64) * 65;

    u64p acc0[8], acc1[8];
#pragma unroll
    for (int q = 0; q < 8; q++) { acc0[q] = 0ull; acc1[q] = 0ull; }

#pragma unroll 4
    for (int j = 0; j < 64; j++) {
        float v0 = r0[j], v1 = r1[j];
        u64p vv0 = pk2(v0, v0);
        u64p vv1 = pk2(v1, v1);
        const float* xb = xi_t + j * 66 + g * 16;
#pragma unroll
        for (int q = 0; q < 8; q++) {
            u64p xq = *reinterpret_cast<const u64p*>(xb + 2 * q);
            acc0[q] = fma2(vv0, xq, acc0[q]);
            acc1[q] = fma2(vv1, xq, acc1[q]);
        }
    }

    float sf = g_sf;
    float* dst = which ? g_B : g_A;
    int n0 = base + slot, n1 = n0 + 64;
#pragma unroll
    for (int q = 0; q < 8; q++) {
        float a, b, c, dq;
        upk2(acc0[q], a, b);
        upk2(acc1[q], c, dq);
        int p0 = g * 16 + 2 * q;
        if (p0 < P) {
            if (n0 < npts) dst[(size_t)p0 * npts + n0] = a * sf;
            if (n1 < npts) dst[(size_t)p0 * npts + n1] = c * sf;
        }
        if (p0 + 1 < P) {
            if (n0 < npts) dst[(size_t)(p0 + 1) * npts + n0] = b * sf;
            if (n1 < npts) dst[(size_t)(p0 + 1) * npts + n1] = dq * sf;
        }
    }
}

// ---------- adjoint: packed Chebyshev, CH=40, kft2 folded, smem lane-slice reduce ----------
__global__ void __launch_bounds__(256) adjoint_kernel(const float* __restrict__ w, int N) {
    int p = blockIdx.x;
    int c = blockIdx.y;
    int z = blockIdx.z;
    int hmax = g_hmax;
    if (hmax < 1) return;
    int k0 = 1 + c * CH;
    if (k0 > hmax) return;

    __shared__ float sP[32 * 81];   // per-lane rows, pad 81 for conflict-free
    int tid = threadIdx.x;
    for (int i = tid; i < 32 * 81; i += 256) sP[i] = 0.f;
    __syncthreads();

    float fk0 = (float)k0;
    const float* arow = g_A + (size_t)p * N;
    int seg = (N + ZSPLIT - 1) / ZSPLIT;
    int st = z * seg;
    int en = st + seg; if (en > N) en = N;

    u64p accv[CH];
#pragma unroll
    for (int j = 0; j < CH; j++) accv[j] = 0ull;

    for (int n0 = st + tid; n0 < en; n0 += 512) {
        int n1 = n0 + 256;
        bool has1 = (n1 < en);
        float a0 = arow[n0];
        float w0 = w[n0];
        float a1 = has1 ? arow[n1] : 0.f;
        float w1 = has1 ? w[n1]   : 0.f;

        float u0s, u0c, u1s, u1c;
        __sincosf(TWO_PI_F * a0, &u0s, &u0c);
        __sincosf(TWO_PI_F * a1, &u1s, &u1c);
        float t0 = fk0 * a0;
        float e0 = fmaf(fk0, a0, -t0);
        float f0 = (t0 - rintf(t0)) + e0;
        float t1 = fk0 * a1;
        float e1 = fmaf(fk0, a1, -t1);
        float f1 = (t1 - rintf(t1)) + e1;
        float z0s, z0c, z1s, z1c;
        __sincosf(TWO_PI_F * f0, &z0s, &z0c);
        __sincosf(TWO_PI_F * f1, &z1s, &z1c);
        float zm0c = fmaf(z0c, u0c,  z0s * u0s);
        float zm0s = fmaf(z0s, u0c, -z0c * u0s);
        float zm1c = fmaf(z1c, u1c,  z1s * u1s);
        float zm1s = fmaf(z1s, u1c, -z1c * u1s);

        u64p v0c_ = pk2(z0c, z0s);
        u64p v0p_ = pk2(-zm0c, -zm0s);
        u64p v1c_ = pk2(z1c, z1s);
        u64p v1p_ = pk2(-zm1c, -zm1s);
        u64p t2v0  = pk2( 2.f * u0c,  2.f * u0c);
        u64p nt2v0 = pk2(-2.f * u0c, -2.f * u0c);
        u64p t2v1  = pk2( 2.f * u1c,  2.f * u1c);
        u64p nt2v1 = pk2(-2.f * u1c, -2.f * u1c);
        u64p wv0  = pk2( w0,  w0);
        u64p nwv0 = pk2(-w0, -w0);
        u64p wv1  = pk2( w1,  w1);
        u64p nwv1 = pk2(-w1, -w1);

#pragma unroll
        for (int j = 0; j < CH; j++) {
            const bool accpos = ((j & 2) == 0);
            const bool rotpos = ((j & 1) == 0);
            accv[j] = fma2(accpos ? wv0 : nwv0, v0c_, accv[j]);
            accv[j] = fma2(accpos ? wv1 : nwv1, v1c_, accv[j]);
            u64p v0n = fma2(rotpos ? t2v0 : nt2v0, v0c_, v0p_);
            v0p_ = v0c_; v0c_ = v0n;
            u64p v1n = fma2(rotpos ? t2v1 : nt2v1, v1c_, v1p_);
            v1p_ = v1c_; v1c_ = v1n;
        }
    }

    // per-lane smem slice accumulation (spread-address shared atomics)
    float* myrow = sP + (tid & 31) * 81;
#pragma unroll
    for (int j = 0; j < CH; j++) {
        float cc, ss;
        upk2(accv[j], cc, ss);
        atomicAdd(myrow + 2 * j, cc);
        atomicAdd(myrow + 2 * j + 1, ss);
    }
    __syncthreads();

    // fold lanes, apply kft2, write to g_CS
    if (tid < 2 * CH) {
        int jj = tid;
        float sum = 0.f;
#pragma unroll
        for (int l = 0; l < 32; l++) sum += sP[l * 81 + jj];
        int j = jj >> 1;
        int k = k0 + j;
        if (k <= 511) {
            float f = g_kft2[k];
            if (f != 0.f)
                atomicAdd(reinterpret_cast<float*>(g_CS + (size_t)p * KPAD + (k - 1)) + (jj & 1),
                          sum * f);
        }
    }
}

// ---------- forward: packed Clenshaw with lower-cutoff anchor ----------
__global__ void __launch_bounds__(256) forward_kernel(float* __restrict__ out,
                                                      int M, int P, int PG) {
    int m = blockIdx.x * blockDim.x + threadIdx.x;
    if (m >= M) return;
    int hmax = g_hmax;
    if (hmax < 1) return;
    int kmin = g_kmin; if (kmin < 1) kmin = 1;
    int KE  = ((hmax + 1) >> 1) << 1;
    int jlo = ((kmin - 1) >> 1) << 1;
    float fklo = (float)(jlo + 1);
    int p0 = blockIdx.y * PG;
    int p1 = p0 + PG; if (p1 > P) p1 = P;
    const u64p negv = pk2(-1.f, -1.f);

    float total = 0.f;
    int p = p0;
    for (; p + 1 < p1; p += 2) {
        float ba = g_B[(size_t)p * M + m];
        float bb = g_B[(size_t)(p + 1) * M + m];
        float sa, ca, sb, cb;
        __sincosf(TWO_PI_F * ba, &sa, &ca);
        __sincosf(TWO_PI_F * bb, &sb, &cb);
        u64p t2a = pk2(2.f * ca, 2.f * ca);
        u64p t2b = pk2(2.f * cb, 2.f * cb);
        u64p a1 = 0ull, a2 = 0ull, b1 = 0ull, b2 = 0ull;
        const float4* CA = reinterpret_cast<const float4*>(g_CS + (size_t)p * KPAD);
        const float4* CB = reinterpret_cast<const float4*>(g_CS + (size_t)(p + 1) * KPAD);
#pragma unroll 4
        for (int j = KE - 2; j >= jlo; j -= 2) {
            float4 fa = __ldg(CA + (j >> 1));
            float4 fb = __ldg(CB + (j >> 1));
            u64p ta = fma2(t2a, a1, pk2(fa.z, fa.w));
            u64p na = fma2(negv, a2, ta);
            a2 = a1; a1 = na;
            u64p tb = fma2(t2b, b1, pk2(fb.z, fb.w));
            u64p nb = fma2(negv, b2, tb);
            b2 = b1; b1 = nb;
            ta = fma2(t2a, a1, pk2(fa.x, fa.y));
            na = fma2(negv, a2, ta);
            a2 = a1; a1 = na;
            tb = fma2(t2b, b1, pk2(fb.x, fb.y));
            nb = fma2(negv, b2, tb);
            b2 = b1; b1 = nb;
        }
        // anchor at klo = jlo+1
        {
            float t = fklo * ba;
            float e = fmaf(fklo, ba, -t);
            float f = (t - rintf(t)) + e;
            float sK, cK;
            __sincosf(TWO_PI_F * f, &sK, &cK);
            float cKm = fmaf(cK, ca,  sK * sa);
            float sKm = fmaf(sK, ca, -cK * sa);
            float a1l, a1h, a2l, a2h;
            upk2(a1, a1l, a1h); upk2(a2, a2l, a2h);
            total += fmaf(a1l, cK, -a2l * cKm) + fmaf(a1h, sK, -a2h * sKm);
        }
        {
            float t = fklo * bb;
            float e = fmaf(fklo, bb, -t);
            float f = (t - rintf(t)) + e;
            float sK, cK;
            __sincosf(TWO_PI_F * f, &sK, &cK);
            float cKm = fmaf(cK, cb,  sK * sb);
            float sKm = fmaf(sK, cb, -cK * sb);
            float b1l, b1h, b2l, b2h;
            upk2(b1, b1l, b1h); upk2(b2, b2l, b2h);
            total += fmaf(b1l, cK, -b2l * cKm) + fmaf(b1h, sK, -b2h * sKm);
        }
    }
    if (p < p1) {   // tail slice
        float ba = g_B[(size_t)p * M + m];
        float sa, ca;
        __sincosf(TWO_PI_F * ba, &sa, &ca);
        u64p t2a = pk2(2.f * ca, 2.f * ca);
        u64p a1 = 0ull, a2 = 0ull;
        const float4* CA = reinterpret_cast<const float4*>(g_CS + (size_t)p * KPAD);
#pragma unroll 4
        for (int j = KE - 2; j >= jlo; j -= 2) {
            float4 fa = __ldg(CA + (j >> 1));
            u64p ta = fma2(t2a, a1, pk2(fa.z, fa.w));
            u64p na = fma2(negv, a2, ta);
            a2 = a1; a1 = na;
            ta = fma2(t2a, a1, pk2(fa.x, fa.y));
            na = fma2(negv, a2, ta);
            a2 = a1; a1 = na;
        }
        float t = fklo * ba;
        float e = fmaf(fklo, ba, -t);
        float f = (t - rintf(t)) + e;
        float sK, cK;
        __sincosf(TWO_PI_F * f, &sK, &cK);
        float cKm = fmaf(cK, ca,  sK * sa);
        float sKm = fmaf(sK, ca, -cK * sa);
        float a1l, a1h, a2l, a2h;
        upk2(a1, a1l, a1h); upk2(a2, a2l, a2h);
        total += fmaf(a1l, cK, -a2l * cKm) + fmaf(a1h, sK, -a2h * sKm);
    }
    atomicAdd(out + m, total);
}

extern "C" void kernel_launch(void* const* d_in, const int* in_sizes, int n_in,
                              void* d_out, int out_size) {
    const float* x     = (const float*)d_in[0];
    const float* y     = (const float*)d_in[1];
    const float* w     = (const float*)d_in[2];
    const float* scale = (const float*)d_in[3];
    const float* xis   = (const float*)d_in[4];
    float* out = (float*)d_out;

    int N = in_sizes[2];
    int d = in_sizes[0] / N;
    int M = out_size;
    int P = in_sizes[4] / d;

    int nb = (N + M + 255) / 256;
    if (nb > 256) nb = 256;   // g_blockmax capacity (N,M <= 8192 here)
    norm_init_kernel<<<nb, 256>>>(x, y, out, N, M, d);
    kft_kernel<<<1, 512>>>(scale, P, (float)d, nb);
    int nmax = (N > M) ? N : M;
    dim3 pgrid((nmax + PROJ_PTS - 1) / PROJ_PTS, 2);
    proj4_kernel<<<pgrid, 256>>>(x, y, xis, N, M, P);
    adjoint_kernel<<<dim3(P, YCH, ZSPLIT), 256>>>(w, N);
    int PG = 8;
    int ngroups = (P + PG - 1) / PG;
    forward_kernel<<<dim3((M + 255) / 256, ngroups), 256>>>(out, M, P, PG);
}

// round 5
// speedup vs baseline: 2.7423x; 1.3436x over previous
#include <cuda_runtime.h>
#include <math.h>

#define TWO_PI_F  6.28318530717958647692f
#define TWO_PI2_F 19.739208802178716f   /* 2*pi^2 */

#define NMAX 8192
#define PMAX 64
#define KPAD 520
#define ACH 16             /* k per adjoint chunk */
#define AYG 4              /* adjoint grid.y (chunk stride) */
#define ZSPLIT 4           /* N-splits in adjoint */
#define PROJ_PTS 128
#define PG 2               /* slices per forward block */

typedef unsigned long long u64p;

// ---------- packed f32x2 helpers ----------
__device__ __forceinline__ u64p pk2(float lo, float hi) {
    u64p r; asm("mov.b64 %0, {%1, %2};" : "=l"(r) : "f"(lo), "f"(hi)); return r;
}
__device__ __forceinline__ void upk2(u64p v, float& lo, float& hi) {
    asm("mov.b64 {%0, %1}, %2;" : "=f"(lo), "=f"(hi) : "l"(v));
}
__device__ __forceinline__ u64p fma2(u64p a, u64p b, u64p c) {
    u64p d; asm("fma.rn.f32x2 %0, %1, %2, %3;" : "=l"(d) : "l"(a), "l"(b), "l"(c)); return d;
}

// ---------- device scratch ----------
__device__ float  g_A[PMAX * NMAX];    // sf * <x_n, xi_p>, [p][n]
__device__ float  g_B[PMAX * NMAX];    // sf * <y_m, xi_p>, [p][m]
__device__ float2 g_CS[PMAX * KPAD];   // (C*kft2, S*kft2), slot j = k-1
__device__ float  g_kft2[KPAD];        // 2*kft(h)/P, thresholded
__device__ float  g_blockmax[256];
__device__ int    g_hmax;
__device__ int    g_kmin;
__device__ float  g_sf;

// ---------- norm + init fused ----------
__global__ void norm_init_kernel(const float* __restrict__ x, const float* __restrict__ y,
                                 float* __restrict__ out, int N, int M, int d) {
    __shared__ float wmax[8];
    int i = blockIdx.x * blockDim.x + threadIdx.x;
    int stride = gridDim.x * blockDim.x;
    float2 z2 = make_float2(0.f, 0.f);
    for (int j = i; j < PMAX * KPAD; j += stride) g_CS[j] = z2;
    for (int j = i; j < M; j += stride) out[j] = 0.f;
    float v = 0.f;
    int T = N + M;
    if (i < T) {
        const float* row = (i < N) ? (x + (size_t)i * d) : (y + (size_t)(i - N) * d);
        float s = 0.f;
        for (int j = 0; j < d; j += 4) {
            float4 q = *reinterpret_cast<const float4*>(row + j);
            s = fmaf(q.x, q.x, s); s = fmaf(q.y, q.y, s);
            s = fmaf(q.z, q.z, s); s = fmaf(q.w, q.w, s);
        }
        v = s;
    }
#pragma unroll
    for (int off = 16; off > 0; off >>= 1)
        v = fmaxf(v, __shfl_xor_sync(0xffffffffu, v, off));
    if ((threadIdx.x & 31) == 0) wmax[threadIdx.x >> 5] = v;
    __syncthreads();
    if (threadIdx.x == 0) {
        float m = wmax[0];
#pragma unroll
        for (int wq = 1; wq < 8; wq++) m = fmaxf(m, wmax[wq]);
        g_blockmax[blockIdx.x] = m;
    }
}

// ---------- Fourier coefficients, cutoff ----------
__global__ void kft_kernel(const float* __restrict__ scale, int P, float dd, int nb) {
    __shared__ float sred[512];
    int tid = threadIdx.x;
    if (tid == 0) { g_hmax = 0; g_kmin = 0x7fffffff; }
    float bm = (tid < nb) ? g_blockmax[tid] : 0.f;
    sred[tid] = bm;
    __syncthreads();
    for (int s = 256; s > 0; s >>= 1) {
        if (tid < s) sred[tid] = fmaxf(sred[tid], sred[tid + s]);
        __syncthreads();
    }
    float nm = sqrtf(sred[0]);
    float sf = 0.3f / nm;
    float sr = scale[0] * sf;
    float s2 = sr * sr;
    int h = tid + 1;
    float kft = 0.f;
    if (h <= 511) {
        float hp = (float)h;
        float logv = 0.5f * dd * logf(TWO_PI2_F * s2)
                   + (dd - 1.f) * logf(hp)
                   - TWO_PI2_F * s2 * hp * hp
                   - lgammaf(0.5f * dd);
        kft = expf(logv);
    }
    __syncthreads();
    sred[tid] = kft;
    __syncthreads();
    for (int s = 256; s > 0; s >>= 1) {
        if (tid < s) sred[tid] = fmaxf(sred[tid], sred[tid + s]);
        __syncthreads();
    }
    float maxv = sred[0];
    float thr = maxv * 1e-10f;
    bool keep = (h <= 511) && (maxv > 0.f) && (kft > thr);
    if (h <= 511) g_kft2[h] = keep ? kft * (2.f / (float)P) : 0.f;
    if (keep) { atomicMax(&g_hmax, h); atomicMin(&g_kmin, h); }
    if (tid == 0) { g_sf = sf; g_kft2[0] = 0.f; }
    if (tid < 8) g_kft2[512 + tid] = 0.f;
}

// ---------- proj4: smem-staged, full P in one pass, packed fma2 ----------
__global__ void __launch_bounds__(256) proj4_kernel(const float* __restrict__ xpts,
                                                    const float* __restrict__ ypts,
                                                    const float* __restrict__ xis,
                                                    int N, int M, int P) {
    __shared__ float xi_t[64 * 66];
    __shared__ float pts_s[PROJ_PTS * 65];
    int tid = threadIdx.x;
    int which = blockIdx.y;
    const float* pts = which ? ypts : xpts;
    int npts = which ? M : N;
    int base = blockIdx.x * PROJ_PTS;

    for (int idx = tid; idx < 64 * 64; idx += 256) {
        int p = idx >> 6, dc = idx & 63;
        xi_t[dc * 66 + p] = (p < P) ? xis[idx] : 0.f;
    }
    for (int idx = tid; idx < PROJ_PTS * 16; idx += 256) {
        int r = idx >> 4, j4 = idx & 15;
        int n = base + r;
        float4 v = make_float4(0.f, 0.f, 0.f, 0.f);
        if (n < npts) v = *reinterpret_cast<const float4*>(pts + (size_t)n * 64 + j4 * 4);
        float* dp = pts_s + r * 65 + j4 * 4;
        dp[0] = v.x; dp[1] = v.y; dp[2] = v.z; dp[3] = v.w;
    }
    __syncthreads();

    int slot = tid & 63;
    int g = tid >> 6;
    const float* r0 = pts_s + slot * 65;
    const float* r1 = pts_s + (slot + 64) * 65;

    u64p acc0[8], acc1[8];
#pragma unroll
    for (int q = 0; q < 8; q++) { acc0[q] = 0ull; acc1[q] = 0ull; }

#pragma unroll 4
    for (int j = 0; j < 64; j++) {
        float v0 = r0[j], v1 = r1[j];
        u64p vv0 = pk2(v0, v0);
        u64p vv1 = pk2(v1, v1);
        const float* xb = xi_t + j * 66 + g * 16;
#pragma unroll
        for (int q = 0; q < 8; q++) {
            u64p xq = *reinterpret_cast<const u64p*>(xb + 2 * q);
            acc0[q] = fma2(vv0, xq, acc0[q]);
            acc1[q] = fma2(vv1, xq, acc1[q]);
        }
    }

    float sf = g_sf;
    float* dst = which ? g_B : g_A;
    int n0 = base + slot, n1 = n0 + 64;
#pragma unroll
    for (int q = 0; q < 8; q++) {
        float a, b, c, dq;
        upk2(acc0[q], a, b);
        upk2(acc1[q], c, dq);
        int p0 = g * 16 + 2 * q;
        if (p0 < P) {
            if (n0 < npts) dst[(size_t)p0 * npts + n0] = a * sf;
            if (n1 < npts) dst[(size_t)p0 * npts + n1] = c * sf;
        }
        if (p0 + 1 < P) {
            if (n0 < npts) dst[(size_t)(p0 + 1) * npts + n0] = b * sf;
            if (n1 < npts) dst[(size_t)(p0 + 1) * npts + n1] = dq * sf;
        }
    }
}

// ---------- adjoint: packed Chebyshev, ACH=16, kmin-offset chunks, grid-strided ----------
__global__ void __launch_bounds__(256) adjoint_kernel(const float* __restrict__ w, int N) {
    int p = blockIdx.x;
    int z = blockIdx.z;
    int hmax = g_hmax;
    if (hmax < 1) return;
    int klo = g_kmin; if (klo < 1) klo = 1;

    __shared__ float sP[32 * 33];   // per-lane rows of 2*ACH, pad to 33
    int tid = threadIdx.x;
    const float* arow = g_A + (size_t)p * N;
    int seg = (N + ZSPLIT - 1) / ZSPLIT;
    int st = z * seg;
    int en = st + seg; if (en > N) en = N;

    for (int c = blockIdx.y; ; c += AYG) {
        int k0 = klo + c * ACH;
        if (k0 > hmax) break;
        float fk0 = (float)k0;

        for (int i = tid; i < 32 * 33; i += 256) sP[i] = 0.f;
        __syncthreads();

        u64p accv[ACH];
#pragma unroll
        for (int j = 0; j < ACH; j++) accv[j] = 0ull;

        for (int n0 = st + tid; n0 < en; n0 += 512) {
            int n1 = n0 + 256;
            bool has1 = (n1 < en);
            float a0 = arow[n0];
            float w0 = w[n0];
            float a1 = has1 ? arow[n1] : 0.f;
            float w1 = has1 ? w[n1]   : 0.f;

            float u0s, u0c, u1s, u1c;
            __sincosf(TWO_PI_F * a0, &u0s, &u0c);
            __sincosf(TWO_PI_F * a1, &u1s, &u1c);
            float t0 = fk0 * a0;
            float e0 = fmaf(fk0, a0, -t0);
            float f0 = (t0 - rintf(t0)) + e0;
            float t1 = fk0 * a1;
            float e1 = fmaf(fk0, a1, -t1);
            float f1 = (t1 - rintf(t1)) + e1;
            float z0s, z0c, z1s, z1c;
            __sincosf(TWO_PI_F * f0, &z0s, &z0c);
            __sincosf(TWO_PI_F * f1, &z1s, &z1c);
            float zm0c = fmaf(z0c, u0c,  z0s * u0s);
            float zm0s = fmaf(z0s, u0c, -z0c * u0s);
            float zm1c = fmaf(z1c, u1c,  z1s * u1s);
            float zm1s = fmaf(z1s, u1c, -z1c * u1s);

            u64p v0c_ = pk2(z0c, z0s);
            u64p v0p_ = pk2(-zm0c, -zm0s);
            u64p v1c_ = pk2(z1c, z1s);
            u64p v1p_ = pk2(-zm1c, -zm1s);
            u64p t2v0  = pk2( 2.f * u0c,  2.f * u0c);
            u64p nt2v0 = pk2(-2.f * u0c, -2.f * u0c);
            u64p t2v1  = pk2( 2.f * u1c,  2.f * u1c);
            u64p nt2v1 = pk2(-2.f * u1c, -2.f * u1c);
            u64p wv0  = pk2( w0,  w0);
            u64p nwv0 = pk2(-w0, -w0);
            u64p wv1  = pk2( w1,  w1);
            u64p nwv1 = pk2(-w1, -w1);

#pragma unroll
            for (int j = 0; j < ACH; j++) {
                const bool accpos = ((j & 2) == 0);
                const bool rotpos = ((j & 1) == 0);
                accv[j] = fma2(accpos ? wv0 : nwv0, v0c_, accv[j]);
                accv[j] = fma2(accpos ? wv1 : nwv1, v1c_, accv[j]);
                u64p v0n = fma2(rotpos ? t2v0 : nt2v0, v0c_, v0p_);
                v0p_ = v0c_; v0c_ = v0n;
                u64p v1n = fma2(rotpos ? t2v1 : nt2v1, v1c_, v1p_);
                v1p_ = v1c_; v1c_ = v1n;
            }
        }

        float* myrow = sP + (tid & 31) * 33;
#pragma unroll
        for (int j = 0; j < ACH; j++) {
            float cc, ss;
            upk2(accv[j], cc, ss);
            atomicAdd(myrow + 2 * j, cc);
            atomicAdd(myrow + 2 * j + 1, ss);
        }
        __syncthreads();

        if (tid < 2 * ACH) {
            int jj = tid;
            float sum = 0.f;
#pragma unroll
            for (int l = 0; l < 32; l++) sum += sP[l * 33 + jj];
            int j = jj >> 1;
            int k = k0 + j;
            if (k <= 511) {
                float f = g_kft2[k];
                if (f != 0.f)
                    atomicAdd(reinterpret_cast<float*>(g_CS + (size_t)p * KPAD + (k - 1)) + (jj & 1),
                              sum * f);
            }
        }
        __syncthreads();
    }
}

// ---------- forward: packed Clenshaw with lower-cutoff anchor, PG=2 ----------
__global__ void __launch_bounds__(256) forward_kernel(float* __restrict__ out,
                                                      int M, int P) {
    int m = blockIdx.x * blockDim.x + threadIdx.x;
    if (m >= M) return;
    int hmax = g_hmax;
    if (hmax < 1) return;
    int kmin = g_kmin; if (kmin < 1) kmin = 1;
    int KE  = ((hmax + 1) >> 1) << 1;
    int jlo = ((kmin - 1) >> 1) << 1;
    float fklo = (float)(jlo + 1);
    int p0 = blockIdx.y * PG;
    int p1 = p0 + PG; if (p1 > P) p1 = P;
    const u64p negv = pk2(-1.f, -1.f);

    float total = 0.f;
    int p = p0;
    for (; p + 1 < p1; p += 2) {
        float ba = g_B[(size_t)p * M + m];
        float bb = g_B[(size_t)(p + 1) * M + m];
        float sa, ca, sb, cb;
        __sincosf(TWO_PI_F * ba, &sa, &ca);
        __sincosf(TWO_PI_F * bb, &sb, &cb);
        u64p t2a = pk2(2.f * ca, 2.f * ca);
        u64p t2b = pk2(2.f * cb, 2.f * cb);
        u64p a1 = 0ull, a2 = 0ull, b1 = 0ull, b2 = 0ull;
        const float4* CA = reinterpret_cast<const float4*>(g_CS + (size_t)p * KPAD);
        const float4* CB = reinterpret_cast<const float4*>(g_CS + (size_t)(p + 1) * KPAD);
#pragma unroll 4
        for (int j = KE - 2; j >= jlo; j -= 2) {
            float4 fa = __ldg(CA + (j >> 1));
            float4 fb = __ldg(CB + (j >> 1));
            u64p ta = fma2(t2a, a1, pk2(fa.z, fa.w));
            u64p na = fma2(negv, a2, ta);
            a2 = a1; a1 = na;
            u64p tb = fma2(t2b, b1, pk2(fb.z, fb.w));
            u64p nb = fma2(negv, b2, tb);
            b2 = b1; b1 = nb;
            ta = fma2(t2a, a1, pk2(fa.x, fa.y));
            na = fma2(negv, a2, ta);
            a2 = a1; a1 = na;
            tb = fma2(t2b, b1, pk2(fb.x, fb.y));
            nb = fma2(negv, b2, tb);
            b2 = b1; b1 = nb;
        }
        {
            float t = fklo * ba;
            float e = fmaf(fklo, ba, -t);
            float f = (t - rintf(t)) + e;
            float sK, cK;
            __sincosf(TWO_PI_F * f, &sK, &cK);
            float cKm = fmaf(cK, ca,  sK * sa);
            float sKm = fmaf(sK, ca, -cK * sa);
            float a1l, a1h, a2l, a2h;
            upk2(a1, a1l, a1h); upk2(a2, a2l, a2h);
            total += fmaf(a1l, cK, -a2l * cKm) + fmaf(a1h, sK, -a2h * sKm);
        }
        {
            float t = fklo * bb;
            float e = fmaf(fklo, bb, -t);
            float f = (t - rintf(t)) + e;
            float sK, cK;
            __sincosf(TWO_PI_F * f, &sK, &cK);
            float cKm = fmaf(cK, cb,  sK * sb);
            float sKm = fmaf(sK, cb, -cK * sb);
            float b1l, b1h, b2l, b2h;
            upk2(b1, b1l, b1h); upk2(b2, b2l, b2h);
            total += fmaf(b1l, cK, -b2l * cKm) + fmaf(b1h, sK, -b2h * sKm);
        }
    }
    if (p < p1) {
        float ba = g_B[(size_t)p * M + m];
        float sa, ca;
        __sincosf(TWO_PI_F * ba, &sa, &ca);
        u64p t2a = pk2(2.f * ca, 2.f * ca);
        u64p a1 = 0ull, a2 = 0ull;
        const float4* CA = reinterpret_cast<const float4*>(g_CS + (size_t)p * KPAD);
#pragma unroll 4
        for (int j = KE - 2; j >= jlo; j -= 2) {
            float4 fa = __ldg(CA + (j >> 1));
            u64p ta = fma2(t2a, a1, pk2(fa.z, fa.w));
            u64p na = fma2(negv, a2, ta);
            a2 = a1; a1 = na;
            ta = fma2(t2a, a1, pk2(fa.x, fa.y));
            na = fma2(negv, a2, ta);
            a2 = a1; a1 = na;
        }
        float t = fklo * ba;
        float e = fmaf(fklo, ba, -t);
        float f = (t - rintf(t)) + e;
        float sK, cK;
        __sincosf(TWO_PI_F * f, &sK, &cK);
        float cKm = fmaf(cK, ca,  sK * sa);
        float sKm = fmaf(sK, ca, -cK * sa);
        float a1l, a1h, a2l, a2h;
        upk2(a1, a1l, a1h); upk2(a2, a2l, a2h);
        total += fmaf(a1l, cK, -a2l * cKm) + fmaf(a1h, sK, -a2h * sKm);
    }
    atomicAdd(out + m, total);
}

extern "C" void kernel_launch(void* const* d_in, const int* in_sizes, int n_in,
                              void* d_out, int out_size) {
    const float* x     = (const float*)d_in[0];
    const float* y     = (const float*)d_in[1];
    const float* w     = (const float*)d_in[2];
    const float* scale = (const float*)d_in[3];
    const float* xis   = (const float*)d_in[4];
    float* out = (float*)d_out;

    int N = in_sizes[2];
    int d = in_sizes[0] / N;
    int M = out_size;
    int P = in_sizes[4] / d;

    int nb = (N + M + 255) / 256;
    if (nb > 256) nb = 256;
    norm_init_kernel<<<nb, 256>>>(x, y, out, N, M, d);
    kft_kernel<<<1, 512>>>(scale, P, (float)d, nb);
    int nmax = (N > M) ? N : M;
    dim3 pgrid((nmax + PROJ_PTS - 1) / PROJ_PTS, 2);
    proj4_kernel<<<pgrid, 256>>>(x, y, xis, N, M, P);
    adjoint_kernel<<<dim3(P, AYG, ZSPLIT), 256>>>(w, N);
    int ngroups = (P + PG - 1) / PG;
    forward_kernel<<<dim3((M + 255) / 256, ngroups), 256>>>(out, M, P);
}